// round 16
// baseline (speedup 1.0000x reference)
#include <cuda_runtime.h>

#define NV 23
#define NN 529          // 23*23
#define TV 12
#define ROWLEN 6348     // N*N*T floats per batch
#define NTHREADS 544    // 17 warps; threads 529..543 idle but sync
#define NBLOCKS 296     // 148 SMs * 2 blocks
#define CHUNK 4         // batches per barrier/ticket

__device__ unsigned int g_ticket;

__global__ void reset_ticket() { g_ticket = 2u * NBLOCKS; }

__global__ __launch_bounds__(NTHREADS, 2)
void gat_kernel(const float* __restrict__ flow,
                const int*   __restrict__ adj,
                const float* __restrict__ W,
                float*       __restrict__ out,
                int B)
{
    __shared__ float dbuf[2][CHUNK][NN];  // staged slices d[m*23+i]
    __shared__ int   adj_s[NN];
    __shared__ int   sticket[2];          // upcoming chunk id, slotted by parity

    const int tid = threadIdx.x;
    const bool act = (tid < NN);
    int i_idx = 0, k_idx = 0;
    if (act) { i_idx = tid / NV; k_idx = tid - i_idx * NV; }

    const int nchunks = (B + CHUNK - 1) / CHUNK;      // 4096

    // ---- adjacency with forced self-loops; grab ticket for C_2 ----
    if (act) {
        int a = adj[tid];
        if (i_idx == k_idx) a = 1;
        adj_s[tid] = a;
    }
    if (tid == 0)
        sticket[1] = (int)atomicAdd(&g_ticket, 1u);   // read in period 0 (p=0)
    __syncthreads();

    // ---- per-thread attention row att[i_idx][k_idx][0..22] in registers ----
    float att[NV];
    if (act) {
        const float* wr = W + tid * NV;
        float mn = 0.0f;                       // = min(min_m W, 0)
        #pragma unroll
        for (int m = 0; m < NV; ++m) {
            att[m] = wr[m];
            mn = fminf(mn, att[m]);
        }
        float s = 0.0f;
        #pragma unroll
        for (int m = 0; m < NV; ++m) {
            float a = (adj_s[k_idx * NV + m] != 0) ? (att[m] - mn) : 0.0f;
            att[m] = a;
            s += a;
        }
        float inv = 1.0f / s;
        #pragma unroll
        for (int m = 0; m < NV; ++m) att[m] *= inv;
    }

    const float* gsrc = flow + tid * TV + (TV - 1);   // this thread's gather point

    // ---- prologue: C_0 -> dbuf[0] ; C_1 -> nvB (held a full period) ----
    int cur  = blockIdx.x;                 // C_0
    int nxt1 = blockIdx.x + NBLOCKS;       // C_1
    float nvB[CHUNK];
    if (act) {
        #pragma unroll
        for (int c = 0; c < CHUNK; ++c) {
            const int b = cur * CHUNK + c;
            dbuf[0][c][tid] = (b < B) ? __ldcs(gsrc + (size_t)b * ROWLEN) : 0.0f;
        }
        #pragma unroll
        for (int c = 0; c < CHUNK; ++c) {
            const int b = nxt1 * CHUNK + c;
            nvB[c] = (nxt1 < nchunks && b < B)
                   ? __ldcs(gsrc + (size_t)b * ROWLEN) : 0.0f;
        }
    }
    __syncthreads();

    // ---- pipelined ticket loop: load C_{i+2}, compute C_i, land C_{i+1} ----
    int p = 0;
    while (cur < nchunks) {
        const int nxt2 = sticket[p ^ 1];              // grabbed last period

        // 1) issue loads for chunk C_{i+2} (consumed NEXT period's landing)
        float nvA[CHUNK];
        if (act) {
            #pragma unroll
            for (int c = 0; c < CHUNK; ++c) {
                const int b = nxt2 * CHUNK + c;
                nvA[c] = (nxt2 < nchunks && b < B)
                       ? __ldcs(gsrc + (size_t)b * ROWLEN) : 0.0f;
            }
        }

        // 2) grab ticket C_{i+3} (hidden under compute + barrier)
        if (tid == 0)
            sticket[p] = (int)atomicAdd(&g_ticket, 1u);

        // 3) compute C_i from staged buffer
        if (act) {
            #pragma unroll
            for (int c = 0; c < CHUNK; ++c) {
                const int b = cur * CHUNK + c;
                if (b < B) {
                    const float* d = dbuf[p][c];
                    float acc = 0.0f;
                    #pragma unroll
                    for (int m = 0; m < NV; ++m)
                        acc = fmaf(att[m], d[m * NV + i_idx], acc);
                    __stcs(out + (size_t)b * NN + tid, acc);   // coalesced
                }
            }
        }

        // 4) land C_{i+1} (loaded a FULL period ago — no scoreboard wait)
        if (act) {
            #pragma unroll
            for (int c = 0; c < CHUNK; ++c)
                dbuf[p ^ 1][c][tid] = nvB[c];
        }
        __syncthreads();

        // rotate pipeline
        cur  = nxt1;
        nxt1 = nxt2;
        if (act) {
            #pragma unroll
            for (int c = 0; c < CHUNK; ++c)
                nvB[c] = nvA[c];
        }
        p ^= 1;
    }
}

extern "C" void kernel_launch(void* const* d_in, const int* in_sizes, int n_in,
                              void* d_out, int out_size) {
    const float* flow = (const float*)d_in[0];   // (B, N, N, T) fp32
    const int*   adj  = (const int*)  d_in[1];   // (N, N) int32
    const float* W    = (const float*)d_in[2];   // (N, N, N) fp32
    float*       out  = (float*)d_out;           // (B, N, N, 1) fp32

    const int B = in_sizes[0] / ROWLEN;
    reset_ticket<<<1, 1>>>();
    gat_kernel<<<NBLOCKS, NTHREADS>>>(flow, adj, W, out, B);
}